// round 1
// baseline (speedup 1.0000x reference)
#include <cuda_runtime.h>
#include <math.h>

// Problem constants (fixed by setup_inputs): B=8, S=4096, H=8, D=128, K=32
#define H_   8
#define D_   128
#define K_   32
#define NTOK 32768               // B*S
#define HD   1024                // H*D
#define NCHUNK 128               // token chunks of 256
#define XS_STRIDE 132            // padded row stride (floats) -> conflict-free LDS.128

// Scratch (device globals: sanctioned workaround for no-alloc rule)
__device__ float g_h[(size_t)NTOK * HD];         // 128 MB intermediate h
__device__ float g_part[H_ * NCHUNK * 256];      // per-chunk partial sum/sumsq
__device__ float g_A[HD];                        // folded BN scale  (0.1*gamma*rs)
__device__ float g_C[HD];                        // folded BN offset (0.1*(beta - mu*rs*gamma))

// ---------------------------------------------------------------------------
// K1: LN -> down-proj -> GELU(exact) -> up-proj; store h; deterministic stats
// grid = (NCHUNK, H), block = 256 (8 warps). Each warp: 32 tokens, lane = token.
// ---------------------------------------------------------------------------
__global__ void __launch_bounds__(256, 1) adapter_k1(
    const float* __restrict__ x,
    const float* __restrict__ lng, const float* __restrict__ lnb,
    const float* __restrict__ wd,  const float* __restrict__ bd,
    const float* __restrict__ wu,  const float* __restrict__ bu)
{
    extern __shared__ float sm[];
    float* wd_s  = sm;                 // [128][32] row d contiguous in k
    float* wu_s  = wd_s + 4096;        // [32][128] row k contiguous in d
    float* lng_s = wu_s + 4096;        // 128
    float* lnb_s = lng_s + 128;        // 128
    float* bd_s  = lnb_s + 128;        // 32
    float* bu_s  = bd_s  + 32;         // 128
    float* st_s  = bu_s  + 128;        // 8 warps * 256
    float* x_all = st_s  + 2048;       // 8 * 32 * 132

    const int h   = blockIdx.y;
    const int tid = threadIdx.x;

    const float* wdh = wd + h * (D_ * K_);
    const float* wuh = wu + h * (K_ * D_);
    for (int i = tid; i < D_ * K_; i += 256) wd_s[i] = wdh[i];
    for (int i = tid; i < K_ * D_; i += 256) wu_s[i] = wuh[i];
    if (tid < D_) {
        lng_s[tid] = lng[h * D_ + tid];
        lnb_s[tid] = lnb[h * D_ + tid];
        bu_s[tid]  = bu[h * D_ + tid];
    }
    if (tid < K_) bd_s[tid] = bd[h * K_ + tid];
    __syncthreads();

    const int w = tid >> 5;
    const int l = tid & 31;
    float* xs = x_all + w * (32 * XS_STRIDE);
    const size_t tok0 = (size_t)blockIdx.x * 256 + (size_t)w * 32;
    const float* xb = x + tok0 * HD + h * D_;

    // Stage 32 tokens (coalesced LDG.128 -> conflict-free STS.128)
    #pragma unroll 4
    for (int t = 0; t < 32; t++) {
        float4 v = *(const float4*)(xb + (size_t)t * HD + l * 4);
        *(float4*)(xs + t * XS_STRIDE + l * 4) = v;
    }
    __syncwarp();

    // LayerNorm stats: lane owns one whole token
    float s = 0.f, ss = 0.f;
    #pragma unroll
    for (int j = 0; j < 32; j++) {
        float4 v = *(const float4*)(xs + l * XS_STRIDE + j * 4);
        s  += (v.x + v.y) + (v.z + v.w);
        ss += v.x*v.x + v.y*v.y + v.z*v.z + v.w*v.w;
    }
    const float mu  = s * (1.f / 128.f);
    const float var = fmaxf(ss * (1.f / 128.f) - mu * mu, 0.f);
    const float rs  = rsqrtf(var + 1e-5f);

    // Down projection: acc[k] = b_down[k] + sum_d xn[d] * wd[d][k]
    float acc[K_];
    #pragma unroll
    for (int k = 0; k < K_; k++) acc[k] = bd_s[k];

    #pragma unroll 4
    for (int dg = 0; dg < 32; dg++) {
        float4 xv = *(const float4*)(xs + l * XS_STRIDE + dg * 4);
        float4 g4 = *(const float4*)(lng_s + dg * 4);
        float4 b4 = *(const float4*)(lnb_s + dg * 4);
        float xn[4];
        xn[0] = (xv.x - mu) * (rs * g4.x) + b4.x;
        xn[1] = (xv.y - mu) * (rs * g4.y) + b4.y;
        xn[2] = (xv.z - mu) * (rs * g4.z) + b4.z;
        xn[3] = (xv.w - mu) * (rs * g4.w) + b4.w;
        #pragma unroll
        for (int j = 0; j < 4; j++) {
            const float* wrow = wd_s + (dg * 4 + j) * K_;
            const float xnj = xn[j];
            #pragma unroll
            for (int kg = 0; kg < 8; kg++) {
                float4 w4 = *(const float4*)(wrow + kg * 4);  // broadcast LDS
                acc[kg*4+0] += xnj * w4.x;
                acc[kg*4+1] += xnj * w4.y;
                acc[kg*4+2] += xnj * w4.z;
                acc[kg*4+3] += xnj * w4.w;
            }
        }
    }

    // Exact GELU: 0.5*x*(1+erf(x/sqrt(2)))
    #pragma unroll
    for (int k = 0; k < K_; k++) {
        float v = acc[k];
        acc[k] = 0.5f * v * (1.f + erff(v * 0.7071067811865476f));
    }

    // Up projection: stream d, write h into xs (x no longer needed)
    #pragma unroll 2
    for (int dg = 0; dg < 32; dg++) {
        float4 o = *(const float4*)(bu_s + dg * 4);
        #pragma unroll
        for (int k = 0; k < K_; k++) {
            float4 w4 = *(const float4*)(wu_s + k * D_ + dg * 4);  // broadcast LDS
            o.x += acc[k] * w4.x;
            o.y += acc[k] * w4.y;
            o.z += acc[k] * w4.z;
            o.w += acc[k] * w4.w;
        }
        *(float4*)(xs + l * XS_STRIDE + dg * 4) = o;
    }
    __syncwarp();

    // Coalesced h store + per-warp BN partials (lane owns d = 4l..4l+3)
    float s0=0,s1=0,s2=0,s3=0,q0=0,q1=0,q2=0,q3=0;
    float* hb = g_h + tok0 * HD + h * D_;
    #pragma unroll 4
    for (int t = 0; t < 32; t++) {
        float4 v = *(const float4*)(xs + t * XS_STRIDE + l * 4);
        *(float4*)(hb + (size_t)t * HD + l * 4) = v;
        s0 += v.x; s1 += v.y; s2 += v.z; s3 += v.w;
        q0 += v.x*v.x; q1 += v.y*v.y; q2 += v.z*v.z; q3 += v.w*v.w;
    }
    float* st = st_s + w * 256;
    *(float4*)(st + l * 4)        = make_float4(s0, s1, s2, s3);
    *(float4*)(st + 128 + l * 4)  = make_float4(q0, q1, q2, q3);
    __syncthreads();

    // Deterministic block reduce over 8 warps -> partials
    float a2 = 0.f;
    #pragma unroll
    for (int w2 = 0; w2 < 8; w2++) a2 += st_s[w2 * 256 + tid];
    g_part[(h * NCHUNK + blockIdx.x) * 256 + tid] = a2;
}

// ---------------------------------------------------------------------------
// K2: fold BN into per-feature affine. grid = (H), block = 128.
// ---------------------------------------------------------------------------
__global__ void adapter_k2(const float* __restrict__ bng, const float* __restrict__ bnb)
{
    const int h = blockIdx.x, d = threadIdx.x;
    float s = 0.f, q = 0.f;
    for (int c = 0; c < NCHUNK; c++) {
        s += g_part[(h * NCHUNK + c) * 256 + d];
        q += g_part[(h * NCHUNK + c) * 256 + d + 128];
    }
    const float inv = 1.f / (float)NTOK;
    const float mu  = s * inv;
    const float var = fmaxf(q * inv - mu * mu, 0.f);
    const float rsv = rsqrtf(var + 1e-5f);
    const float g = bng[h * D_ + d], b = bnb[h * D_ + d];
    g_A[h * D_ + d] = 0.1f * g * rsv;
    g_C[h * D_ + d] = 0.1f * (b - mu * rsv * g);
}

// ---------------------------------------------------------------------------
// K3: out = h*A + C + x (elementwise, streaming). One float4 per thread.
// ---------------------------------------------------------------------------
__global__ void __launch_bounds__(256) adapter_k3(const float* __restrict__ x,
                                                  float* __restrict__ out)
{
    const size_t i = (size_t)blockIdx.x * 256 + threadIdx.x;
    const float4 hv = ((const float4*)g_h)[i];
    const float4 xv = ((const float4*)x)[i];
    const int col = (int)((i * 4) & (HD - 1));
    const float4 a = *(const float4*)(g_A + col);
    const float4 c = *(const float4*)(g_C + col);
    float4 r;
    r.x = hv.x * a.x + c.x + xv.x;
    r.y = hv.y * a.y + c.y + xv.y;
    r.z = hv.z * a.z + c.z + xv.z;
    r.w = hv.w * a.w + c.w + xv.w;
    ((float4*)out)[i] = r;
}

// ---------------------------------------------------------------------------
extern "C" void kernel_launch(void* const* d_in, const int* in_sizes, int n_in,
                              void* d_out, int out_size)
{
    const float* x   = (const float*)d_in[0];
    const float* lng = (const float*)d_in[1];
    const float* lnb = (const float*)d_in[2];
    const float* wd  = (const float*)d_in[3];
    const float* bd  = (const float*)d_in[4];
    const float* wu  = (const float*)d_in[5];
    const float* bu  = (const float*)d_in[6];
    const float* bng = (const float*)d_in[7];
    const float* bnb = (const float*)d_in[8];
    float* out = (float*)d_out;

    const size_t smem = (size_t)(4096 + 4096 + 128 + 128 + 32 + 128 + 2048
                                 + 8 * 32 * XS_STRIDE) * sizeof(float);  // ~174 KB
    cudaFuncSetAttribute(adapter_k1, cudaFuncAttributeMaxDynamicSharedMemorySize, (int)smem);

    adapter_k1<<<dim3(NCHUNK, H_), 256, smem>>>(x, lng, lnb, wd, bd, wu, bu);
    adapter_k2<<<H_, 128>>>(bng, bnb);
    adapter_k3<<<(NTOK * HD) / (256 * 4), 256>>>(x, out);
}

// round 2
// speedup vs baseline: 1.1069x; 1.1069x over previous
#include <cuda_runtime.h>
#include <math.h>

// Problem constants (fixed by setup_inputs): B=8, S=4096, H=8, D=128, K=32
#define H_   8
#define D_   128
#define K_   32
#define NTOK 32768               // B*S
#define HD   1024                // H*D
#define TOKB 256                 // tokens per block (8 warps x 32)
#define NCHUNK 128               // NTOK / TOKB
#define R4   5                   // stage row stride in float4 (conflict-free)

// Scratch (device globals: sanctioned workaround for no-alloc rule)
__device__ float g_h[(size_t)NTOK * HD];         // 128 MB intermediate h
__device__ float g_part[H_ * NCHUNK * 256];      // per-chunk partial sum/sumsq
__device__ float g_A[HD];                        // folded BN scale
__device__ float g_C[HD];                        // folded BN offset

// ---------------------------------------------------------------------------
// K1: fused LN+down-proj (single pass over x) -> GELU -> up-proj; h + stats.
// grid = (NCHUNK, H), block = 256 (8 warps). Warp: 32 tokens, lane = token.
// Identity: acc[k] = rs*(S[k] - mu*P[k]) + Q[k],
//   S[k] = sum_d x[d]*(g[d]*wd[d][k]), P[k] = sum_d g[d]*wd[d][k],
//   Q[k] = bd[k] + sum_d b[d]*wd[d][k]
// ---------------------------------------------------------------------------
__global__ void __launch_bounds__(256, 3) adapter_k1(
    const float* __restrict__ x,
    const float* __restrict__ lng, const float* __restrict__ lnb,
    const float* __restrict__ wd,  const float* __restrict__ bd,
    const float* __restrict__ wu,  const float* __restrict__ bu)
{
    extern __shared__ float sm[];
    float* wdg_s = sm;                  // [128][32] gamma-folded down weights
    float* wu_s  = wdg_s + 4096;        // [32][128]
    float* lng_s = wu_s + 4096;         // 128
    float* lnb_s = lng_s + 128;         // 128
    float* bu_s  = lnb_s + 128;         // 128
    float* P_s   = bu_s + 128;          // 32
    float* Q_s   = P_s + 32;            // 32
    float* st_s  = Q_s + 32;            // 8 warps * 256 (BN partials)
    float* stg   = st_s + 2048;         // 8 warps * 32 * (R4*4) = 5120
    // total = 15812 floats = 63.25 KB -> 3 CTAs/SM

    const int h   = blockIdx.y;
    const int tid = threadIdx.x;

    if (tid < D_) {
        lng_s[tid] = lng[h * D_ + tid];
        lnb_s[tid] = lnb[h * D_ + tid];
        bu_s[tid]  = bu[h * D_ + tid];
    }
    __syncthreads();

    const float* wdh = wd + h * (D_ * K_);
    const float* wuh = wu + h * (K_ * D_);
    for (int i = tid; i < 4096; i += 256) {
        wdg_s[i] = lng_s[i >> 5] * wdh[i];
        wu_s[i]  = wuh[i];
    }
    __syncthreads();

    if (tid < K_) {
        float p = 0.f, q = bd[h * K_ + tid];
        #pragma unroll 4
        for (int d = 0; d < D_; d++) {
            p += wdg_s[d * K_ + tid];
            q += lnb_s[d] * wdh[d * K_ + tid];
        }
        P_s[tid] = p; Q_s[tid] = q;
    }
    __syncthreads();

    const int w = tid >> 5, l = tid & 31;
    const int lm8 = l & 7, ld8 = l >> 3;
    float4* sg = (float4*)(stg + w * (32 * R4 * 4));
    const size_t tok0 = (size_t)blockIdx.x * TOKB + (size_t)w * 32;
    const float* xb = x + tok0 * HD + h * D_;

    // ---- Pass 1: fused LN-stats + down-projection over 8 chunks of 16 d ----
    float s = 0.f, ss = 0.f;
    float S[K_];
    #pragma unroll
    for (int k = 0; k < K_; k++) S[k] = 0.f;

    for (int c = 0; c < 8; c++) {
        // stage chunk: lane loads token t = i*8+lm8, float4 slot ld8
        #pragma unroll
        for (int i = 0; i < 4; i++) {
            int t = i * 8 + lm8;
            float4 v = *(const float4*)(xb + (size_t)t * HD + c * 16 + ld8 * 4);
            sg[t * R4 + ld8] = v;
        }
        __syncwarp();
        #pragma unroll
        for (int j = 0; j < 4; j++) {
            float4 xv = sg[l * R4 + j];
            float xa[4] = {xv.x, xv.y, xv.z, xv.w};
            #pragma unroll
            for (int e = 0; e < 4; e++) {
                const float xd = xa[e];
                s += xd; ss += xd * xd;
                const float* wr = wdg_s + (c * 16 + j * 4 + e) * K_;
                #pragma unroll
                for (int kg = 0; kg < 8; kg++) {
                    float4 w4 = *(const float4*)(wr + kg * 4);  // broadcast LDS
                    S[kg*4+0] += xd * w4.x;
                    S[kg*4+1] += xd * w4.y;
                    S[kg*4+2] += xd * w4.z;
                    S[kg*4+3] += xd * w4.w;
                }
            }
        }
        __syncwarp();
    }

    const float mu  = s * (1.f / 128.f);
    const float var = fmaxf(ss * (1.f / 128.f) - mu * mu, 0.f);
    const float rs  = rsqrtf(var + 1e-5f);

    // finalize down-proj + exact GELU
    #pragma unroll
    for (int k = 0; k < K_; k++) {
        float v = rs * (S[k] - mu * P_s[k]) + Q_s[k];
        S[k] = 0.5f * v * (1.f + erff(v * 0.7071067811865476f));
    }

    // ---- Pass 2: up-projection, coalesced h store, BN partials ----
    float* stw = st_s + w * 256;
    float* hb = g_h + tok0 * HD + h * D_;
    for (int c = 0; c < 8; c++) {
        #pragma unroll
        for (int j = 0; j < 4; j++) {
            float4 o = *(const float4*)(bu_s + c * 16 + j * 4);
            #pragma unroll
            for (int k = 0; k < K_; k++) {
                float4 w4 = *(const float4*)(wu_s + k * D_ + c * 16 + j * 4);
                o.x += S[k] * w4.x;
                o.y += S[k] * w4.y;
                o.z += S[k] * w4.z;
                o.w += S[k] * w4.w;
            }
            sg[l * R4 + j] = o;
        }
        __syncwarp();
        float ps0=0,ps1=0,ps2=0,ps3=0,pq0=0,pq1=0,pq2=0,pq3=0;
        #pragma unroll
        for (int i = 0; i < 4; i++) {
            int t = i * 8 + lm8;
            float4 v = sg[t * R4 + ld8];
            *(float4*)(hb + (size_t)t * HD + c * 16 + ld8 * 4) = v;
            ps0 += v.x; ps1 += v.y; ps2 += v.z; ps3 += v.w;
            pq0 += v.x*v.x; pq1 += v.y*v.y; pq2 += v.z*v.z; pq3 += v.w*v.w;
        }
        #pragma unroll
        for (int m = 1; m < 8; m <<= 1) {
            ps0 += __shfl_xor_sync(0xffffffffu, ps0, m);
            ps1 += __shfl_xor_sync(0xffffffffu, ps1, m);
            ps2 += __shfl_xor_sync(0xffffffffu, ps2, m);
            ps3 += __shfl_xor_sync(0xffffffffu, ps3, m);
            pq0 += __shfl_xor_sync(0xffffffffu, pq0, m);
            pq1 += __shfl_xor_sync(0xffffffffu, pq1, m);
            pq2 += __shfl_xor_sync(0xffffffffu, pq2, m);
            pq3 += __shfl_xor_sync(0xffffffffu, pq3, m);
        }
        if (lm8 == 0) {
            int f = c * 16 + ld8 * 4;
            *(float4*)(stw + f)        = make_float4(ps0, ps1, ps2, ps3);
            *(float4*)(stw + 128 + f)  = make_float4(pq0, pq1, pq2, pq3);
        }
        __syncwarp();
    }
    __syncthreads();

    // deterministic block reduce over 8 warps -> per-chunk partials
    float a2 = 0.f;
    #pragma unroll
    for (int w2 = 0; w2 < 8; w2++) a2 += st_s[w2 * 256 + tid];
    g_part[(h * NCHUNK + blockIdx.x) * 256 + tid] = a2;
}

// ---------------------------------------------------------------------------
// K2: fold BN into per-feature affine. grid = (H), block = 128.
// ---------------------------------------------------------------------------
__global__ void adapter_k2(const float* __restrict__ bng, const float* __restrict__ bnb)
{
    const int h = blockIdx.x, d = threadIdx.x;
    float s = 0.f, q = 0.f;
    for (int c = 0; c < NCHUNK; c++) {
        s += g_part[(h * NCHUNK + c) * 256 + d];
        q += g_part[(h * NCHUNK + c) * 256 + d + 128];
    }
    const float inv = 1.f / (float)NTOK;
    const float mu  = s * inv;
    const float var = fmaxf(q * inv - mu * mu, 0.f);
    const float rsv = rsqrtf(var + 1e-5f);
    const float g = bng[h * D_ + d], b = bnb[h * D_ + d];
    g_A[h * D_ + d] = 0.1f * g * rsv;
    g_C[h * D_ + d] = 0.1f * (b - mu * rsv * g);
}

// ---------------------------------------------------------------------------
// K3: out = h*A + C + x (elementwise, streaming).
// ---------------------------------------------------------------------------
__global__ void __launch_bounds__(256) adapter_k3(const float* __restrict__ x,
                                                  float* __restrict__ out)
{
    const size_t i = (size_t)blockIdx.x * 256 + threadIdx.x;
    const float4 hv = ((const float4*)g_h)[i];
    const float4 xv = ((const float4*)x)[i];
    const int col = (int)((i * 4) & (HD - 1));
    const float4 a = *(const float4*)(g_A + col);
    const float4 c = *(const float4*)(g_C + col);
    float4 r;
    r.x = hv.x * a.x + c.x + xv.x;
    r.y = hv.y * a.y + c.y + xv.y;
    r.z = hv.z * a.z + c.z + xv.z;
    r.w = hv.w * a.w + c.w + xv.w;
    ((float4*)out)[i] = r;
}

// ---------------------------------------------------------------------------
extern "C" void kernel_launch(void* const* d_in, const int* in_sizes, int n_in,
                              void* d_out, int out_size)
{
    const float* x   = (const float*)d_in[0];
    const float* lng = (const float*)d_in[1];
    const float* lnb = (const float*)d_in[2];
    const float* wd  = (const float*)d_in[3];
    const float* bd  = (const float*)d_in[4];
    const float* wu  = (const float*)d_in[5];
    const float* bu  = (const float*)d_in[6];
    const float* bng = (const float*)d_in[7];
    const float* bnb = (const float*)d_in[8];
    float* out = (float*)d_out;

    const size_t smem = (size_t)15812 * sizeof(float);  // 63.25 KB
    cudaFuncSetAttribute(adapter_k1, cudaFuncAttributeMaxDynamicSharedMemorySize, (int)smem);

    adapter_k1<<<dim3(NCHUNK, H_), 256, smem>>>(x, lng, lnb, wd, bd, wu, bu);
    adapter_k2<<<H_, 128>>>(bng, bnb);
    adapter_k3<<<(NTOK * HD) / (256 * 4), 256>>>(x, out);
}

// round 3
// speedup vs baseline: 1.1853x; 1.0709x over previous
#include <cuda_runtime.h>
#include <math.h>

// Problem constants: B=8, S=4096, H=8, D=128, K=32
#define H_   8
#define D_   128
#define K_   32
#define NTOK 32768
#define HD   1024
#define TOKB 512                 // tokens per block (8 warps x 64)
#define NCHUNK 64                // NTOK / TOKB
#define R4   5                   // staging row stride in float4 (conflict-free)

typedef unsigned long long u64;

__device__ __forceinline__ u64 ffma2(u64 a, u64 b, u64 c) {
    u64 d;
    asm("fma.rn.f32x2 %0, %1, %2, %3;" : "=l"(d) : "l"(a), "l"(b), "l"(c));
    return d;
}
__device__ __forceinline__ u64 dup2(float x) {
    u64 d;
    asm("mov.b64 %0, {%1, %1};" : "=l"(d) : "r"(__float_as_uint(x)));
    return d;
}
__device__ __forceinline__ float2 unpack2(u64 v) {
    float2 r;
    asm("mov.b64 {%0, %1}, %2;" : "=f"(r.x), "=f"(r.y) : "l"(v));
    return r;
}

// Scratch
__device__ float g_h[(size_t)NTOK * HD];
__device__ float g_part[H_ * NCHUNK * 256];
__device__ float g_A[HD];
__device__ float g_C[HD];

// ---------------------------------------------------------------------------
// K1: fused LN+down (one pass) -> GELU -> up; 2 tokens/lane, packed f32x2 FMA.
// grid = (NCHUNK, H), block = 256 (8 warps). Warp: 64 tokens.
// acc[k] = rs*(S[k] - mu*P[k]) + Q[k]
// ---------------------------------------------------------------------------
__global__ void __launch_bounds__(256, 2) adapter_k1(
    const float* __restrict__ x,
    const float* __restrict__ lng, const float* __restrict__ lnb,
    const float* __restrict__ wd,  const float* __restrict__ bd,
    const float* __restrict__ wu,  const float* __restrict__ bu)
{
    extern __shared__ float sm[];
    float* wdg_s = sm;                  // [128][32] gamma-folded down weights
    float* wu_s  = wdg_s + 4096;        // [32][128]
    float* lng_s = wu_s + 4096;         // 128
    float* lnb_s = lng_s + 128;         // 128
    float* bu_s  = lnb_s + 128;         // 128
    float* P_s   = bu_s + 128;          // 32
    float* Q_s   = P_s + 32;            // 32
    float* st_s  = Q_s + 32;            // 8 warps * 256 (BN partials)
    float* stg   = st_s + 2048;         // 8 warps * 64 * R4 * 4 = 10240
    // total 20928 floats = 83.7 KB -> 2 CTAs/SM

    const int h   = blockIdx.y;
    const int tid = threadIdx.x;

    if (tid < D_) {
        lng_s[tid] = lng[h * D_ + tid];
        lnb_s[tid] = lnb[h * D_ + tid];
        bu_s[tid]  = bu[h * D_ + tid];
    }
    __syncthreads();

    const float* wdh = wd + h * (D_ * K_);
    const float* wuh = wu + h * (K_ * D_);
    for (int i = tid; i < 4096; i += 256) {
        wdg_s[i] = lng_s[i >> 5] * wdh[i];
        wu_s[i]  = wuh[i];
    }
    __syncthreads();

    if (tid < K_) {
        float p = 0.f, q = bd[h * K_ + tid];
        #pragma unroll 4
        for (int d = 0; d < D_; d++) {
            p += wdg_s[d * K_ + tid];
            q += lnb_s[d] * wdh[d * K_ + tid];
        }
        P_s[tid] = p; Q_s[tid] = q;
    }
    __syncthreads();

    const int w = tid >> 5, l = tid & 31;
    const int lm8 = l & 7, ld8 = l >> 3;
    float4* sg = (float4*)(stg + w * (64 * R4 * 4));
    u64*    sgu = (u64*)sg;
    const size_t tok0 = (size_t)blockIdx.x * TOKB + (size_t)w * 64;
    const float* xb = x + tok0 * HD + h * D_;

    // ---- Pass 1: LN stats + down-proj, 8 chunks of 16 d, 2 tokens/lane ----
    float s0 = 0.f, ss0 = 0.f, s1 = 0.f, ss1 = 0.f;
    u64 A0[16], A1[16];
    #pragma unroll
    for (int m = 0; m < 16; m++) { A0[m] = 0ull; A1[m] = 0ull; }

    for (int c = 0; c < 8; c++) {
        #pragma unroll
        for (int i = 0; i < 8; i++) {
            int t = i * 8 + lm8;
            float4 v = *(const float4*)(xb + (size_t)t * HD + c * 16 + ld8 * 4);
            sg[t * R4 + ld8] = v;
        }
        __syncwarp();
        #pragma unroll
        for (int j = 0; j < 4; j++) {
            float4 xv0 = sg[l * R4 + j];
            float4 xv1 = sg[(l + 32) * R4 + j];
            s0  += (xv0.x + xv0.y) + (xv0.z + xv0.w);
            ss0 += xv0.x*xv0.x + xv0.y*xv0.y + xv0.z*xv0.z + xv0.w*xv0.w;
            s1  += (xv1.x + xv1.y) + (xv1.z + xv1.w);
            ss1 += xv1.x*xv1.x + xv1.y*xv1.y + xv1.z*xv1.z + xv1.w*xv1.w;
            float xa0[4] = {xv0.x, xv0.y, xv0.z, xv0.w};
            float xa1[4] = {xv1.x, xv1.y, xv1.z, xv1.w};
            #pragma unroll
            for (int e = 0; e < 4; e++) {
                const u64 d0 = dup2(xa0[e]);
                const u64 d1 = dup2(xa1[e]);
                const u64* wr = (const u64*)(wdg_s + (c * 16 + j * 4 + e) * K_);
                #pragma unroll
                for (int g = 0; g < 8; g++) {
                    ulonglong2 w2 = *(const ulonglong2*)(wr + g * 2); // LDS.128 bcast
                    A0[g*2+0] = ffma2(d0, w2.x, A0[g*2+0]);
                    A0[g*2+1] = ffma2(d0, w2.y, A0[g*2+1]);
                    A1[g*2+0] = ffma2(d1, w2.x, A1[g*2+0]);
                    A1[g*2+1] = ffma2(d1, w2.y, A1[g*2+1]);
                }
            }
        }
        __syncwarp();
    }

    const float mu0 = s0 * (1.f/128.f);
    const float rs0 = rsqrtf(fmaxf(ss0 * (1.f/128.f) - mu0*mu0, 0.f) + 1e-5f);
    const float mu1 = s1 * (1.f/128.f);
    const float rs1 = rsqrtf(fmaxf(ss1 * (1.f/128.f) - mu1*mu1, 0.f) + 1e-5f);

    // finalize down-proj + exact GELU (A0[m] holds k=2m,2m+1)
    float a0[K_], a1[K_];
    #pragma unroll
    for (int m = 0; m < 16; m++) {
        float2 f0 = unpack2(A0[m]);
        float2 f1 = unpack2(A1[m]);
        a0[2*m] = f0.x; a0[2*m+1] = f0.y;
        a1[2*m] = f1.x; a1[2*m+1] = f1.y;
    }
    #pragma unroll
    for (int k = 0; k < K_; k++) {
        float v0 = rs0 * (a0[k] - mu0 * P_s[k]) + Q_s[k];
        float v1 = rs1 * (a1[k] - mu1 * P_s[k]) + Q_s[k];
        a0[k] = 0.5f * v0 * (1.f + erff(v0 * 0.7071067811865476f));
        a1[k] = 0.5f * v1 * (1.f + erff(v1 * 0.7071067811865476f));
    }

    // ---- Pass 2: up-proj (packed), coalesced h store, BN partials ----
    float* stw = st_s + w * 256;
    float* hb = g_h + tok0 * HD + h * D_;
    for (int c = 0; c < 8; c++) {
        u64 O0[8], O1[8];
        const u64* bup = (const u64*)(bu_s + c * 16);
        #pragma unroll
        for (int p = 0; p < 8; p++) { O0[p] = bup[p]; O1[p] = bup[p]; }
        #pragma unroll 8
        for (int k = 0; k < K_; k++) {
            const u64 a0d = dup2(a0[k]);
            const u64 a1d = dup2(a1[k]);
            const u64* wr = (const u64*)(wu_s + k * D_ + c * 16);
            #pragma unroll
            for (int p = 0; p < 8; p += 2) {
                ulonglong2 w2 = *(const ulonglong2*)(wr + p);   // LDS.128 bcast
                O0[p]   = ffma2(a0d, w2.x, O0[p]);
                O0[p+1] = ffma2(a0d, w2.y, O0[p+1]);
                O1[p]   = ffma2(a1d, w2.x, O1[p]);
                O1[p+1] = ffma2(a1d, w2.y, O1[p+1]);
            }
        }
        #pragma unroll
        for (int j = 0; j < 4; j++) {
            sgu[(l * R4 + j) * 2]            = O0[2*j];
            sgu[(l * R4 + j) * 2 + 1]        = O0[2*j+1];
            sgu[((l + 32) * R4 + j) * 2]     = O1[2*j];
            sgu[((l + 32) * R4 + j) * 2 + 1] = O1[2*j+1];
        }
        __syncwarp();
        float ps0=0,ps1=0,ps2=0,ps3=0,pq0=0,pq1=0,pq2=0,pq3=0;
        #pragma unroll
        for (int i = 0; i < 8; i++) {
            int t = i * 8 + lm8;
            float4 v = sg[t * R4 + ld8];
            *(float4*)(hb + (size_t)t * HD + c * 16 + ld8 * 4) = v;
            ps0 += v.x; ps1 += v.y; ps2 += v.z; ps3 += v.w;
            pq0 += v.x*v.x; pq1 += v.y*v.y; pq2 += v.z*v.z; pq3 += v.w*v.w;
        }
        #pragma unroll
        for (int m = 1; m < 8; m <<= 1) {
            ps0 += __shfl_xor_sync(0xffffffffu, ps0, m);
            ps1 += __shfl_xor_sync(0xffffffffu, ps1, m);
            ps2 += __shfl_xor_sync(0xffffffffu, ps2, m);
            ps3 += __shfl_xor_sync(0xffffffffu, ps3, m);
            pq0 += __shfl_xor_sync(0xffffffffu, pq0, m);
            pq1 += __shfl_xor_sync(0xffffffffu, pq1, m);
            pq2 += __shfl_xor_sync(0xffffffffu, pq2, m);
            pq3 += __shfl_xor_sync(0xffffffffu, pq3, m);
        }
        if (lm8 == 0) {
            int f = c * 16 + ld8 * 4;
            *(float4*)(stw + f)       = make_float4(ps0, ps1, ps2, ps3);
            *(float4*)(stw + 128 + f) = make_float4(pq0, pq1, pq2, pq3);
        }
        __syncwarp();
    }
    __syncthreads();

    float a2 = 0.f;
    #pragma unroll
    for (int w2 = 0; w2 < 8; w2++) a2 += st_s[w2 * 256 + tid];
    g_part[(h * NCHUNK + blockIdx.x) * 256 + tid] = a2;
}

// ---------------------------------------------------------------------------
__global__ void adapter_k2(const float* __restrict__ bng, const float* __restrict__ bnb)
{
    const int h = blockIdx.x, d = threadIdx.x;
    float s = 0.f, q = 0.f;
    for (int c = 0; c < NCHUNK; c++) {
        s += g_part[(h * NCHUNK + c) * 256 + d];
        q += g_part[(h * NCHUNK + c) * 256 + d + 128];
    }
    const float inv = 1.f / (float)NTOK;
    const float mu  = s * inv;
    const float var = fmaxf(q * inv - mu * mu, 0.f);
    const float rsv = rsqrtf(var + 1e-5f);
    const float g = bng[h * D_ + d], b = bnb[h * D_ + d];
    g_A[h * D_ + d] = 0.1f * g * rsv;
    g_C[h * D_ + d] = 0.1f * (b - mu * rsv * g);
}

// ---------------------------------------------------------------------------
__global__ void __launch_bounds__(256) adapter_k3(const float* __restrict__ x,
                                                  float* __restrict__ out)
{
    const size_t i = (size_t)blockIdx.x * 256 + threadIdx.x;
    const float4 hv = ((const float4*)g_h)[i];
    const float4 xv = ((const float4*)x)[i];
    const int col = (int)((i * 4) & (HD - 1));
    const float4 a = *(const float4*)(g_A + col);
    const float4 c = *(const float4*)(g_C + col);
    float4 r;
    r.x = hv.x * a.x + c.x + xv.x;
    r.y = hv.y * a.y + c.y + xv.y;
    r.z = hv.z * a.z + c.z + xv.z;
    r.w = hv.w * a.w + c.w + xv.w;
    ((float4*)out)[i] = r;
}

// ---------------------------------------------------------------------------
extern "C" void kernel_launch(void* const* d_in, const int* in_sizes, int n_in,
                              void* d_out, int out_size)
{
    const float* x   = (const float*)d_in[0];
    const float* lng = (const float*)d_in[1];
    const float* lnb = (const float*)d_in[2];
    const float* wd  = (const float*)d_in[3];
    const float* bd  = (const float*)d_in[4];
    const float* wu  = (const float*)d_in[5];
    const float* bu  = (const float*)d_in[6];
    const float* bng = (const float*)d_in[7];
    const float* bnb = (const float*)d_in[8];
    float* out = (float*)d_out;

    const size_t smem = (size_t)20928 * sizeof(float);  // 83.7 KB
    cudaFuncSetAttribute(adapter_k1, cudaFuncAttributeMaxDynamicSharedMemorySize, (int)smem);

    adapter_k1<<<dim3(NCHUNK, H_), 256, smem>>>(x, lng, lnb, wd, bd, wu, bu);
    adapter_k2<<<H_, 128>>>(bng, bnb);
    adapter_k3<<<(NTOK * HD) / (256 * 4), 256>>>(x, out);
}

// round 4
// speedup vs baseline: 1.1870x; 1.0014x over previous
#include <cuda_runtime.h>
#include <math.h>

// Problem constants: B=8, S=4096, H=8, D=128, K=32
#define H_   8
#define D_   128
#define K_   32
#define NTOK 32768
#define HD   1024
#define TOKB 512                 // tokens per block (8 warps x 64)
#define NCHUNK 64                // NTOK / TOKB
#define R4   5                   // staging row stride in float4 (conflict-free)

typedef unsigned long long u64;

__device__ __forceinline__ u64 ffma2(u64 a, u64 b, u64 c) {
    u64 d;
    asm("fma.rn.f32x2 %0, %1, %2, %3;" : "=l"(d) : "l"(a), "l"(b), "l"(c));
    return d;
}
__device__ __forceinline__ u64 dup2(float x) {
    u64 d;
    asm("mov.b64 %0, {%1, %1};" : "=l"(d) : "r"(__float_as_uint(x)));
    return d;
}
__device__ __forceinline__ float2 unpack2(u64 v) {
    float2 r;
    asm("mov.b64 {%0, %1}, %2;" : "=f"(r.x), "=f"(r.y) : "l"(v));
    return r;
}

// Scratch
__device__ float g_h[(size_t)NTOK * HD];
__device__ float g_part[H_ * NCHUNK * 256];
__device__ float g_A[HD];
__device__ float g_C[HD];

// ---------------------------------------------------------------------------
// K1: fused LN+down (one pass) -> GELU -> up; 2 tokens/lane, packed f32x2 FMA.
// grid = (NCHUNK, H), block = 256 (8 warps). Warp: 64 tokens.
// acc[k] = rs*(S[k] - mu*P[k]) + Q[k]
// ---------------------------------------------------------------------------
__global__ void __launch_bounds__(256, 2) adapter_k1(
    const float* __restrict__ x,
    const float* __restrict__ lng, const float* __restrict__ lnb,
    const float* __restrict__ wd,  const float* __restrict__ bd,
    const float* __restrict__ wu,  const float* __restrict__ bu)
{
    extern __shared__ float sm[];
    float* wdg_s = sm;                  // [128][32] gamma-folded down weights
    float* wu_s  = wdg_s + 4096;        // [32][128]
    float* lng_s = wu_s + 4096;         // 128
    float* lnb_s = lng_s + 128;         // 128
    float* bu_s  = lnb_s + 128;         // 128
    float* P_s   = bu_s + 128;          // 32
    float* Q_s   = P_s + 32;            // 32
    float* st_s  = Q_s + 32;            // 8 warps * 256 (BN partials)
    float* stg   = st_s + 2048;         // 8 warps * 64 * R4 * 4 = 10240
    // total 20928 floats = 83.7 KB -> 2 CTAs/SM

    const int h   = blockIdx.y;
    const int tid = threadIdx.x;

    if (tid < D_) {
        lng_s[tid] = lng[h * D_ + tid];
        lnb_s[tid] = lnb[h * D_ + tid];
        bu_s[tid]  = bu[h * D_ + tid];
    }
    __syncthreads();

    const float* wdh = wd + h * (D_ * K_);
    const float* wuh = wu + h * (K_ * D_);
    for (int i = tid; i < 4096; i += 256) {
        wdg_s[i] = lng_s[i >> 5] * wdh[i];
        wu_s[i]  = wuh[i];
    }
    __syncthreads();

    if (tid < K_) {
        float p = 0.f, q = bd[h * K_ + tid];
        #pragma unroll 4
        for (int d = 0; d < D_; d++) {
            p += wdg_s[d * K_ + tid];
            q += lnb_s[d] * wdh[d * K_ + tid];
        }
        P_s[tid] = p; Q_s[tid] = q;
    }
    __syncthreads();

    const int w = tid >> 5, l = tid & 31;
    const int lm8 = l & 7, ld8 = l >> 3;
    float4* sg = (float4*)(stg + w * (64 * R4 * 4));
    u64*    sgu = (u64*)sg;
    const size_t tok0 = (size_t)blockIdx.x * TOKB + (size_t)w * 64;
    const float* xb = x + tok0 * HD + h * D_;

    // ---- Pass 1: LN stats + down-proj, 8 chunks of 16 d, 2 tokens/lane ----
    float s0 = 0.f, ss0 = 0.f, s1 = 0.f, ss1 = 0.f;
    u64 A0[16], A1[16];
    #pragma unroll
    for (int m = 0; m < 16; m++) { A0[m] = 0ull; A1[m] = 0ull; }

    for (int c = 0; c < 8; c++) {
        #pragma unroll
        for (int i = 0; i < 8; i++) {
            int t = i * 8 + lm8;
            float4 v = *(const float4*)(xb + (size_t)t * HD + c * 16 + ld8 * 4);
            sg[t * R4 + ld8] = v;
        }
        __syncwarp();
        #pragma unroll
        for (int j = 0; j < 4; j++) {
            float4 xv0 = sg[l * R4 + j];
            float4 xv1 = sg[(l + 32) * R4 + j];
            s0  += (xv0.x + xv0.y) + (xv0.z + xv0.w);
            ss0 += xv0.x*xv0.x + xv0.y*xv0.y + xv0.z*xv0.z + xv0.w*xv0.w;
            s1  += (xv1.x + xv1.y) + (xv1.z + xv1.w);
            ss1 += xv1.x*xv1.x + xv1.y*xv1.y + xv1.z*xv1.z + xv1.w*xv1.w;
            float xa0[4] = {xv0.x, xv0.y, xv0.z, xv0.w};
            float xa1[4] = {xv1.x, xv1.y, xv1.z, xv1.w};
            #pragma unroll
            for (int e = 0; e < 4; e++) {
                const u64 d0 = dup2(xa0[e]);
                const u64 d1 = dup2(xa1[e]);
                const u64* wr = (const u64*)(wdg_s + (c * 16 + j * 4 + e) * K_);
                #pragma unroll
                for (int g = 0; g < 8; g++) {
                    ulonglong2 w2 = *(const ulonglong2*)(wr + g * 2); // LDS.128 bcast
                    A0[g*2+0] = ffma2(d0, w2.x, A0[g*2+0]);
                    A0[g*2+1] = ffma2(d0, w2.y, A0[g*2+1]);
                    A1[g*2+0] = ffma2(d1, w2.x, A1[g*2+0]);
                    A1[g*2+1] = ffma2(d1, w2.y, A1[g*2+1]);
                }
            }
        }
        __syncwarp();
    }

    const float mu0 = s0 * (1.f/128.f);
    const float rs0 = rsqrtf(fmaxf(ss0 * (1.f/128.f) - mu0*mu0, 0.f) + 1e-5f);
    const float mu1 = s1 * (1.f/128.f);
    const float rs1 = rsqrtf(fmaxf(ss1 * (1.f/128.f) - mu1*mu1, 0.f) + 1e-5f);

    // finalize down-proj + exact GELU (A0[m] holds k=2m,2m+1)
    float a0[K_], a1[K_];
    #pragma unroll
    for (int m = 0; m < 16; m++) {
        float2 f0 = unpack2(A0[m]);
        float2 f1 = unpack2(A1[m]);
        a0[2*m] = f0.x; a0[2*m+1] = f0.y;
        a1[2*m] = f1.x; a1[2*m+1] = f1.y;
    }
    #pragma unroll
    for (int k = 0; k < K_; k++) {
        float v0 = rs0 * (a0[k] - mu0 * P_s[k]) + Q_s[k];
        float v1 = rs1 * (a1[k] - mu1 * P_s[k]) + Q_s[k];
        a0[k] = 0.5f * v0 * (1.f + erff(v0 * 0.7071067811865476f));
        a1[k] = 0.5f * v1 * (1.f + erff(v1 * 0.7071067811865476f));
    }

    // ---- Pass 2: up-proj (packed), coalesced h store, BN partials ----
    float* stw = st_s + w * 256;
    float* hb = g_h + tok0 * HD + h * D_;
    for (int c = 0; c < 8; c++) {
        u64 O0[8], O1[8];
        const u64* bup = (const u64*)(bu_s + c * 16);
        #pragma unroll
        for (int p = 0; p < 8; p++) { O0[p] = bup[p]; O1[p] = bup[p]; }
        #pragma unroll 8
        for (int k = 0; k < K_; k++) {
            const u64 a0d = dup2(a0[k]);
            const u64 a1d = dup2(a1[k]);
            const u64* wr = (const u64*)(wu_s + k * D_ + c * 16);
            #pragma unroll
            for (int p = 0; p < 8; p += 2) {
                ulonglong2 w2 = *(const ulonglong2*)(wr + p);   // LDS.128 bcast
                O0[p]   = ffma2(a0d, w2.x, O0[p]);
                O0[p+1] = ffma2(a0d, w2.y, O0[p+1]);
                O1[p]   = ffma2(a1d, w2.x, O1[p]);
                O1[p+1] = ffma2(a1d, w2.y, O1[p+1]);
            }
        }
        #pragma unroll
        for (int j = 0; j < 4; j++) {
            sgu[(l * R4 + j) * 2]            = O0[2*j];
            sgu[(l * R4 + j) * 2 + 1]        = O0[2*j+1];
            sgu[((l + 32) * R4 + j) * 2]     = O1[2*j];
            sgu[((l + 32) * R4 + j) * 2 + 1] = O1[2*j+1];
        }
        __syncwarp();
        float ps0=0,ps1=0,ps2=0,ps3=0,pq0=0,pq1=0,pq2=0,pq3=0;
        #pragma unroll
        for (int i = 0; i < 8; i++) {
            int t = i * 8 + lm8;
            float4 v = sg[t * R4 + ld8];
            *(float4*)(hb + (size_t)t * HD + c * 16 + ld8 * 4) = v;
            ps0 += v.x; ps1 += v.y; ps2 += v.z; ps3 += v.w;
            pq0 += v.x*v.x; pq1 += v.y*v.y; pq2 += v.z*v.z; pq3 += v.w*v.w;
        }
        #pragma unroll
        for (int m = 1; m < 8; m <<= 1) {
            ps0 += __shfl_xor_sync(0xffffffffu, ps0, m);
            ps1 += __shfl_xor_sync(0xffffffffu, ps1, m);
            ps2 += __shfl_xor_sync(0xffffffffu, ps2, m);
            ps3 += __shfl_xor_sync(0xffffffffu, ps3, m);
            pq0 += __shfl_xor_sync(0xffffffffu, pq0, m);
            pq1 += __shfl_xor_sync(0xffffffffu, pq1, m);
            pq2 += __shfl_xor_sync(0xffffffffu, pq2, m);
            pq3 += __shfl_xor_sync(0xffffffffu, pq3, m);
        }
        if (lm8 == 0) {
            int f = c * 16 + ld8 * 4;
            *(float4*)(stw + f)       = make_float4(ps0, ps1, ps2, ps3);
            *(float4*)(stw + 128 + f) = make_float4(pq0, pq1, pq2, pq3);
        }
        __syncwarp();
    }
    __syncthreads();

    float a2 = 0.f;
    #pragma unroll
    for (int w2 = 0; w2 < 8; w2++) a2 += st_s[w2 * 256 + tid];
    g_part[(h * NCHUNK + blockIdx.x) * 256 + tid] = a2;
}

// ---------------------------------------------------------------------------
__global__ void adapter_k2(const float* __restrict__ bng, const float* __restrict__ bnb)
{
    const int h = blockIdx.x, d = threadIdx.x;
    float s = 0.f, q = 0.f;
    for (int c = 0; c < NCHUNK; c++) {
        s += g_part[(h * NCHUNK + c) * 256 + d];
        q += g_part[(h * NCHUNK + c) * 256 + d + 128];
    }
    const float inv = 1.f / (float)NTOK;
    const float mu  = s * inv;
    const float var = fmaxf(q * inv - mu * mu, 0.f);
    const float rsv = rsqrtf(var + 1e-5f);
    const float g = bng[h * D_ + d], b = bnb[h * D_ + d];
    g_A[h * D_ + d] = 0.1f * g * rsv;
    g_C[h * D_ + d] = 0.1f * (b - mu * rsv * g);
}

// ---------------------------------------------------------------------------
__global__ void __launch_bounds__(256) adapter_k3(const float* __restrict__ x,
                                                  float* __restrict__ out)
{
    const size_t i = (size_t)blockIdx.x * 256 + threadIdx.x;
    const float4 hv = ((const float4*)g_h)[i];
    const float4 xv = ((const float4*)x)[i];
    const int col = (int)((i * 4) & (HD - 1));
    const float4 a = *(const float4*)(g_A + col);
    const float4 c = *(const float4*)(g_C + col);
    float4 r;
    r.x = hv.x * a.x + c.x + xv.x;
    r.y = hv.y * a.y + c.y + xv.y;
    r.z = hv.z * a.z + c.z + xv.z;
    r.w = hv.w * a.w + c.w + xv.w;
    ((float4*)out)[i] = r;
}

// ---------------------------------------------------------------------------
extern "C" void kernel_launch(void* const* d_in, const int* in_sizes, int n_in,
                              void* d_out, int out_size)
{
    const float* x   = (const float*)d_in[0];
    const float* lng = (const float*)d_in[1];
    const float* lnb = (const float*)d_in[2];
    const float* wd  = (const float*)d_in[3];
    const float* bd  = (const float*)d_in[4];
    const float* wu  = (const float*)d_in[5];
    const float* bu  = (const float*)d_in[6];
    const float* bng = (const float*)d_in[7];
    const float* bnb = (const float*)d_in[8];
    float* out = (float*)d_out;

    const size_t smem = (size_t)20928 * sizeof(float);  // 83.7 KB
    cudaFuncSetAttribute(adapter_k1, cudaFuncAttributeMaxDynamicSharedMemorySize, (int)smem);

    adapter_k1<<<dim3(NCHUNK, H_), 256, smem>>>(x, lng, lnb, wd, bd, wu, bu);
    adapter_k2<<<H_, 128>>>(bng, bnb);
    adapter_k3<<<(NTOK * HD) / (256 * 4), 256>>>(x, out);
}

// round 6
// speedup vs baseline: 1.2671x; 1.0675x over previous
#include <cuda_runtime.h>
#include <cuda_bf16.h>
#include <math.h>
#include <stdint.h>

// Problem constants: B=8, S=4096, H=8, D=128, K=32
#define H_   8
#define D_   128
#define K_   32
#define NTOK 32768
#define HD   1024
#define TOKB 512                 // tokens per block (8 warps x 64)
#define NCHUNK 64                // NTOK / TOKB
#define R4   5                   // staging row stride in float4 (conflict-free)

typedef unsigned long long u64;

__device__ __forceinline__ u64 ffma2(u64 a, u64 b, u64 c) {
    u64 d;
    asm("fma.rn.f32x2 %0, %1, %2, %3;" : "=l"(d) : "l"(a), "l"(b), "l"(c));
    return d;
}
__device__ __forceinline__ u64 dup2(float x) {
    u64 d;
    asm("mov.b64 %0, {%1, %1};" : "=l"(d) : "r"(__float_as_uint(x)));
    return d;
}
__device__ __forceinline__ float2 unpack2(u64 v) {
    float2 r;
    asm("mov.b64 {%0, %1}, %2;" : "=f"(r.x), "=f"(r.y) : "l"(v));
    return r;
}
// bf16x2 word -> packed f32x2 {low = pk<<16 (exact), high = pk (<=1 ulp noise)}
__device__ __forceinline__ u64 bfp(uint32_t pk) {
    u64 d;
    asm("{\n\t.reg .b32 lo;\n\tshl.b32 lo, %1, 16;\n\tmov.b64 %0, {lo, %1};\n\t}"
        : "=l"(d) : "r"(pk));
    return d;
}
__device__ __forceinline__ uint32_t pack_bf16(float hi, float lo) {
    uint32_t r;
    asm("cvt.rn.bf16x2.f32 %0, %1, %2;" : "=r"(r) : "f"(hi), "f"(lo));
    return r;
}

// Scratch
__device__ __nv_bfloat16 g_h[(size_t)NTOK * HD];   // 64 MB intermediate h (bf16)
__device__ float g_part[H_ * NCHUNK * 256];
__device__ float g_A[HD];
__device__ float g_C[HD];

// SMEM layout (bytes)
#define SO_WD   0        // 8192: bf16 [128 d][32 k] gamma-folded down weights
#define SO_WU   8192     // 8192: bf16 [32 k][128 d] up weights
#define SO_LNG  16384    // 512
#define SO_LNB  16896    // 512
#define SO_BU   17408    // 512 (fp32 up bias)
#define SO_P    17920    // 128
#define SO_Q    18048    // 128
#define SO_ST   18176    // 8192: 8 warps * 256 BN partials
#define SO_STG  26368    // 40960: 8 warps * 64 tok * R4 float4
#define SMEM_BYTES 67328

// ---------------------------------------------------------------------------
// K1: fused LN+down (one pass) -> GELU -> up; 2 tokens/lane, bf16 weights.
// grid = (NCHUNK, H), block = 256 (8 warps). Warp: 64 tokens.
// acc[k] = rs*(S[k] - mu*P[k]) + Q[k]
// ---------------------------------------------------------------------------
__global__ void __launch_bounds__(256, 2) adapter_k1(
    const float* __restrict__ x,
    const float* __restrict__ lng, const float* __restrict__ lnb,
    const float* __restrict__ wd,  const float* __restrict__ bd,
    const float* __restrict__ wu,  const float* __restrict__ bu)
{
    extern __shared__ __align__(16) char smc[];
    __nv_bfloat16* wdg_s = (__nv_bfloat16*)(smc + SO_WD);
    __nv_bfloat16* wuu_s = (__nv_bfloat16*)(smc + SO_WU);
    float* lng_s = (float*)(smc + SO_LNG);
    float* lnb_s = (float*)(smc + SO_LNB);
    float* bu_s  = (float*)(smc + SO_BU);
    float* P_s   = (float*)(smc + SO_P);
    float* Q_s   = (float*)(smc + SO_Q);
    float* st_s  = (float*)(smc + SO_ST);
    float* stg   = (float*)(smc + SO_STG);

    const int h   = blockIdx.y;
    const int tid = threadIdx.x;

    if (tid < D_) {
        lng_s[tid] = lng[h * D_ + tid];
        lnb_s[tid] = lnb[h * D_ + tid];
        bu_s[tid]  = bu[h * D_ + tid];
    }
    __syncthreads();

    const float* wdh = wd + h * (D_ * K_);
    const float* wuh = wu + h * (K_ * D_);
    for (int i = tid; i < 4096; i += 256) {
        wdg_s[i] = __float2bfloat16(lng_s[i >> 5] * wdh[i]);   // [d][k]
        wuu_s[i] = __float2bfloat16(wuh[i]);                   // [k][d]
    }
    __syncthreads();

    if (tid < K_) {
        float p = 0.f, q = bd[h * K_ + tid];
        #pragma unroll 4
        for (int d = 0; d < D_; d++) {
            p += __bfloat162float(wdg_s[d * K_ + tid]);
            q += lnb_s[d] * wdh[d * K_ + tid];
        }
        P_s[tid] = p; Q_s[tid] = q;
    }
    __syncthreads();

    const int w = tid >> 5, l = tid & 31;
    const int lm8 = l & 7, ld8 = l >> 3;
    float4* sg = (float4*)(stg + w * (64 * R4 * 4));
    u64*    sgu = (u64*)sg;
    const size_t tok0 = (size_t)blockIdx.x * TOKB + (size_t)w * 64;
    const float* xb = x + tok0 * HD + h * D_;

    // ---- Pass 1: LN stats + down-proj, 8 chunks of 16 d, 2 tokens/lane ----
    float s0 = 0.f, ss0 = 0.f, s1 = 0.f, ss1 = 0.f;
    u64 A0[16], A1[16];
    #pragma unroll
    for (int m = 0; m < 16; m++) { A0[m] = 0ull; A1[m] = 0ull; }

    for (int c = 0; c < 8; c++) {
        #pragma unroll
        for (int i = 0; i < 8; i++) {
            int t = i * 8 + lm8;
            float4 v = *(const float4*)(xb + (size_t)t * HD + c * 16 + ld8 * 4);
            sg[t * R4 + ld8] = v;
        }
        __syncwarp();
        #pragma unroll
        for (int j = 0; j < 4; j++) {
            float4 xv0 = sg[l * R4 + j];
            float4 xv1 = sg[(l + 32) * R4 + j];
            s0  += (xv0.x + xv0.y) + (xv0.z + xv0.w);
            ss0 += xv0.x*xv0.x + xv0.y*xv0.y + xv0.z*xv0.z + xv0.w*xv0.w;
            s1  += (xv1.x + xv1.y) + (xv1.z + xv1.w);
            ss1 += xv1.x*xv1.x + xv1.y*xv1.y + xv1.z*xv1.z + xv1.w*xv1.w;
            float xa0[4] = {xv0.x, xv0.y, xv0.z, xv0.w};
            float xa1[4] = {xv1.x, xv1.y, xv1.z, xv1.w};
            #pragma unroll
            for (int e = 0; e < 4; e++) {
                const u64 d0 = dup2(xa0[e]);
                const u64 d1 = dup2(xa1[e]);
                const uint4* wr = (const uint4*)(wdg_s + (c * 16 + j * 4 + e) * K_);
                #pragma unroll
                for (int g = 0; g < 2; g++) {            // 2 LDS.128 = 32 bf16 wts
                    uint4 wv = wr[g];                    // k = g*16 .. g*16+7 pairs
                    u64 w0 = bfp(wv.x), w1 = bfp(wv.y), w2 = bfp(wv.z), w3 = bfp(wv.w);
                    A0[g*8+0] = ffma2(d0, w0, A0[g*8+0]);
                    A0[g*8+1] = ffma2(d0, w1, A0[g*8+1]);
                    A0[g*8+2] = ffma2(d0, w2, A0[g*8+2]);
                    A0[g*8+3] = ffma2(d0, w3, A0[g*8+3]);
                    A1[g*8+0] = ffma2(d1, w0, A1[g*8+0]);
                    A1[g*8+1] = ffma2(d1, w1, A1[g*8+1]);
                    A1[g*8+2] = ffma2(d1, w2, A1[g*8+2]);
                    A1[g*8+3] = ffma2(d1, w3, A1[g*8+3]);
                }
                #pragma unroll
                for (int g = 0; g < 2; g++) {
                    uint4 wv = wr[g + 2];                // upper 16 k (uint4 index 2,3)
                    u64 w0 = bfp(wv.x), w1 = bfp(wv.y), w2 = bfp(wv.z), w3 = bfp(wv.w);
                    A0[8+g*8+4-8+4] = A0[8+g*8+4-8+4];   // (no-op guard removed below)
                    A0[g*8+4] = ffma2(d0, w0, A0[g*8+4]);
                    A0[g*8+5] = ffma2(d0, w1, A0[g*8+5]);
                    A0[g*8+6] = ffma2(d0, w2, A0[g*8+6]);
                    A0[g*8+7] = ffma2(d0, w3, A0[g*8+7]);
                    A1[g*8+4] = ffma2(d1, w0, A1[g*8+4]);
                    A1[g*8+5] = ffma2(d1, w1, A1[g*8+5]);
                    A1[g*8+6] = ffma2(d1, w2, A1[g*8+6]);
                    A1[g*8+7] = ffma2(d1, w3, A1[g*8+7]);
                }
            }
        }
        __syncwarp();
    }

    const float mu0 = s0 * (1.f/128.f);
    const float rs0 = rsqrtf(fmaxf(ss0 * (1.f/128.f) - mu0*mu0, 0.f) + 1e-5f);
    const float mu1 = s1 * (1.f/128.f);
    const float rs1 = rsqrtf(fmaxf(ss1 * (1.f/128.f) - mu1*mu1, 0.f) + 1e-5f);

    // A-index -> k mapping: uint4 index u (0..3), word w (0..3):
    //   m = (u&1)*8 + (u>>1)*4 + w covers k pair (u*8 + w*2, +1)
    // From loops above: first g-loop (u=g in {0,1}) wrote m = g*8 + w  -> k = g*8+2w
    //                   second (u=g+2)             wrote m = g*8+4+w  -> k = (g+2)*8+2w
    float a0[K_], a1[K_];
    #pragma unroll
    for (int g = 0; g < 2; g++) {
        #pragma unroll
        for (int wv = 0; wv < 4; wv++) {
            { float2 f0 = unpack2(A0[g*8 + wv]);     float2 f1 = unpack2(A1[g*8 + wv]);
              int k0 = g*8 + wv*2;
              a0[k0] = f0.x; a0[k0+1] = f0.y; a1[k0] = f1.x; a1[k0+1] = f1.y; }
            { float2 f0 = unpack2(A0[g*8 + 4 + wv]); float2 f1 = unpack2(A1[g*8 + 4 + wv]);
              int k0 = (g+2)*8 + wv*2;
              a0[k0] = f0.x; a0[k0+1] = f0.y; a1[k0] = f1.x; a1[k0+1] = f1.y; }
        }
    }
    #pragma unroll
    for (int k = 0; k < K_; k++) {
        float v0 = rs0 * (a0[k] - mu0 * P_s[k]) + Q_s[k];
        float v1 = rs1 * (a1[k] - mu1 * P_s[k]) + Q_s[k];
        a0[k] = 0.5f * v0 * (1.f + erff(v0 * 0.7071067811865476f));
        a1[k] = 0.5f * v1 * (1.f + erff(v1 * 0.7071067811865476f));
    }

    // ---- Pass 2: up-proj (bf16 wts), bf16 h store, BN partials ----
    float* stw = st_s + w * 256;
    __nv_bfloat16* hb = g_h + tok0 * HD + h * D_;
    for (int c = 0; c < 8; c++) {
        u64 O0[8], O1[8];
        const u64* bup = (const u64*)(bu_s + c * 16);
        #pragma unroll
        for (int p = 0; p < 8; p++) { O0[p] = bup[p]; O1[p] = bup[p]; }
        #pragma unroll 8
        for (int k = 0; k < K_; k++) {
            const u64 a0d = dup2(a0[k]);
            const u64 a1d = dup2(a1[k]);
            const uint4* wr = (const uint4*)(wuu_s + k * D_ + c * 16);
            uint4 wa = wr[0];                    // d pairs 0..3 of chunk
            uint4 wb = wr[1];                    // d pairs 4..7
            u64 w0 = bfp(wa.x), w1 = bfp(wa.y), w2 = bfp(wa.z), w3 = bfp(wa.w);
            u64 w4 = bfp(wb.x), w5 = bfp(wb.y), w6 = bfp(wb.z), w7 = bfp(wb.w);
            O0[0] = ffma2(a0d, w0, O0[0]); O0[1] = ffma2(a0d, w1, O0[1]);
            O0[2] = ffma2(a0d, w2, O0[2]); O0[3] = ffma2(a0d, w3, O0[3]);
            O0[4] = ffma2(a0d, w4, O0[4]); O0[5] = ffma2(a0d, w5, O0[5]);
            O0[6] = ffma2(a0d, w6, O0[6]); O0[7] = ffma2(a0d, w7, O0[7]);
            O1[0] = ffma2(a1d, w0, O1[0]); O1[1] = ffma2(a1d, w1, O1[1]);
            O1[2] = ffma2(a1d, w2, O1[2]); O1[3] = ffma2(a1d, w3, O1[3]);
            O1[4] = ffma2(a1d, w4, O1[4]); O1[5] = ffma2(a1d, w5, O1[5]);
            O1[6] = ffma2(a1d, w6, O1[6]); O1[7] = ffma2(a1d, w7, O1[7]);
        }
        #pragma unroll
        for (int j = 0; j < 4; j++) {
            sgu[(l * R4 + j) * 2]            = O0[2*j];
            sgu[(l * R4 + j) * 2 + 1]        = O0[2*j+1];
            sgu[((l + 32) * R4 + j) * 2]     = O1[2*j];
            sgu[((l + 32) * R4 + j) * 2 + 1] = O1[2*j+1];
        }
        __syncwarp();
        float ps0=0,ps1=0,ps2=0,ps3=0,pq0=0,pq1=0,pq2=0,pq3=0;
        #pragma unroll
        for (int i = 0; i < 8; i++) {
            int t = i * 8 + lm8;
            float4 v = sg[t * R4 + ld8];
            uint32_t p0 = pack_bf16(v.y, v.x);
            uint32_t p1 = pack_bf16(v.w, v.z);
            // stats on the ROUNDED values (consistent with stored h)
            float2 r0 = __bfloat1622float2(*(__nv_bfloat162*)&p0);
            float2 r1 = __bfloat1622float2(*(__nv_bfloat162*)&p1);
            *(uint2*)(hb + (size_t)t * HD + c * 16 + ld8 * 4) = make_uint2(p0, p1);
            ps0 += r0.x; ps1 += r0.y; ps2 += r1.x; ps3 += r1.y;
            pq0 += r0.x*r0.x; pq1 += r0.y*r0.y; pq2 += r1.x*r1.x; pq3 += r1.y*r1.y;
        }
        #pragma unroll
        for (int m = 1; m < 8; m <<= 1) {
            ps0 += __shfl_xor_sync(0xffffffffu, ps0, m);
            ps1 += __shfl_xor_sync(0xffffffffu, ps1, m);
            ps2 += __shfl_xor_sync(0xffffffffu, ps2, m);
            ps3 += __shfl_xor_sync(0xffffffffu, ps3, m);
            pq0 += __shfl_xor_sync(0xffffffffu, pq0, m);
            pq1 += __shfl_xor_sync(0xffffffffu, pq1, m);
            pq2 += __shfl_xor_sync(0xffffffffu, pq2, m);
            pq3 += __shfl_xor_sync(0xffffffffu, pq3, m);
        }
        if (lm8 == 0) {
            int f = c * 16 + ld8 * 4;
            *(float4*)(stw + f)       = make_float4(ps0, ps1, ps2, ps3);
            *(float4*)(stw + 128 + f) = make_float4(pq0, pq1, pq2, pq3);
        }
        __syncwarp();
    }
    __syncthreads();

    float a2 = 0.f;
    #pragma unroll
    for (int w2 = 0; w2 < 8; w2++) a2 += st_s[w2 * 256 + tid];
    g_part[(h * NCHUNK + blockIdx.x) * 256 + tid] = a2;
}

// ---------------------------------------------------------------------------
__global__ void adapter_k2(const float* __restrict__ bng, const float* __restrict__ bnb)
{
    const int h = blockIdx.x, d = threadIdx.x;
    float s = 0.f, q = 0.f;
    for (int c = 0; c < NCHUNK; c++) {
        s += g_part[(h * NCHUNK + c) * 256 + d];
        q += g_part[(h * NCHUNK + c) * 256 + d + 128];
    }
    const float inv = 1.f / (float)NTOK;
    const float mu  = s * inv;
    const float var = fmaxf(q * inv - mu * mu, 0.f);
    const float rsv = rsqrtf(var + 1e-5f);
    const float g = bng[h * D_ + d], b = bnb[h * D_ + d];
    g_A[h * D_ + d] = 0.1f * g * rsv;
    g_C[h * D_ + d] = 0.1f * (b - mu * rsv * g);
}

// ---------------------------------------------------------------------------
// K3: out = h*A + C + x (h is bf16; streaming).
// ---------------------------------------------------------------------------
__global__ void __launch_bounds__(256) adapter_k3(const float* __restrict__ x,
                                                  float* __restrict__ out)
{
    const size_t i = (size_t)blockIdx.x * 256 + threadIdx.x;
    const uint2 hraw = ((const uint2*)g_h)[i];
    const float4 xv = ((const float4*)x)[i];
    float2 f01 = __bfloat1622float2(*(const __nv_bfloat162*)&hraw.x);
    float2 f23 = __bfloat1622float2(*(const __nv_bfloat162*)&hraw.y);
    const int col = (int)((i * 4) & (HD - 1));
    const float4 a = *(const float4*)(g_A + col);
    const float4 c = *(const float4*)(g_C + col);
    float4 r;
    r.x = f01.x * a.x + c.x + xv.x;
    r.y = f01.y * a.y + c.y + xv.y;
    r.z = f23.x * a.z + c.z + xv.z;
    r.w = f23.y * a.w + c.w + xv.w;
    ((float4*)out)[i] = r;
}

// ---------------------------------------------------------------------------
extern "C" void kernel_launch(void* const* d_in, const int* in_sizes, int n_in,
                              void* d_out, int out_size)
{
    const float* x   = (const float*)d_in[0];
    const float* lng = (const float*)d_in[1];
    const float* lnb = (const float*)d_in[2];
    const float* wd  = (const float*)d_in[3];
    const float* bd  = (const float*)d_in[4];
    const float* wu  = (const float*)d_in[5];
    const float* bu  = (const float*)d_in[6];
    const float* bng = (const float*)d_in[7];
    const float* bnb = (const float*)d_in[8];
    float* out = (float*)d_out;

    cudaFuncSetAttribute(adapter_k1, cudaFuncAttributeMaxDynamicSharedMemorySize, SMEM_BYTES);

    adapter_k1<<<dim3(NCHUNK, H_), 256, SMEM_BYTES>>>(x, lng, lnb, wd, bd, wu, bu);
    adapter_k2<<<H_, 128>>>(bng, bnb);
    adapter_k3<<<(NTOK * HD) / (256 * 4), 256>>>(x, out);
}